// round 1
// baseline (speedup 1.0000x reference)
#include <cuda_runtime.h>

#define D_MODEL 1024
#define NHEAD   16
#define HDIM    64
#define BATCH   2
#define SEQ     2048
#define MROWS   (BATCH*SEQ)       // 4096
#define QKVDIM  (3*D_MODEL)       // 3072

// Scratch (no cudaMalloc allowed)
__device__ float g_qkv [BATCH*SEQ*QKVDIM];   // 50 MB
__device__ float g_attn[BATCH*SEQ*D_MODEL];  // 16 MB

// ---------------------------------------------------------------------------
// C[m][n] = sum_k A[m*K+k] * B[n*K+k]   (both K-major; classic SGEMM-TN)
// BM=BN=128, BK=16, 256 threads, 8x8 per-thread tile.
// ---------------------------------------------------------------------------
__global__ void __launch_bounds__(256) sgemm_tn(
    const float* __restrict__ A, const float* __restrict__ B,
    float* __restrict__ C, int M, int N, int K)
{
    const int BK = 16;
    const int LDT = 132;                 // padded tile stride (words)
    __shared__ float As[BK * LDT];       // As[kk][m], m in [0,128)
    __shared__ float Bs[BK * LDT];       // Bs[kk][n]

    const int tid = threadIdx.x;
    const int bm  = blockIdx.y * 128;
    const int bn  = blockIdx.x * 128;

    const int lr = tid >> 2;             // 0..63
    const int lc = (tid & 3) << 2;       // 0,4,8,12
    const int ty = tid >> 4;             // 0..15
    const int tx = tid & 15;             // 0..15

    const float* a0p = A + (size_t)(bm + lr)      * K + lc;
    const float* a1p = A + (size_t)(bm + lr + 64) * K + lc;
    const float* b0p = B + (size_t)(bn + lr)      * K + lc;
    const float* b1p = B + (size_t)(bn + lr + 64) * K + lc;

    float acc[8][8];
    #pragma unroll
    for (int i = 0; i < 8; i++)
        #pragma unroll
        for (int j = 0; j < 8; j++) acc[i][j] = 0.f;

    for (int k0 = 0; k0 < K; k0 += BK) {
        float4 a0 = *(const float4*)(a0p + k0);
        float4 a1 = *(const float4*)(a1p + k0);
        float4 b0 = *(const float4*)(b0p + k0);
        float4 b1 = *(const float4*)(b1p + k0);

        __syncthreads();
        As[(lc+0)*LDT + lr]      = a0.x;
        As[(lc+1)*LDT + lr]      = a0.y;
        As[(lc+2)*LDT + lr]      = a0.z;
        As[(lc+3)*LDT + lr]      = a0.w;
        As[(lc+0)*LDT + lr + 64] = a1.x;
        As[(lc+1)*LDT + lr + 64] = a1.y;
        As[(lc+2)*LDT + lr + 64] = a1.z;
        As[(lc+3)*LDT + lr + 64] = a1.w;
        Bs[(lc+0)*LDT + lr]      = b0.x;
        Bs[(lc+1)*LDT + lr]      = b0.y;
        Bs[(lc+2)*LDT + lr]      = b0.z;
        Bs[(lc+3)*LDT + lr]      = b0.w;
        Bs[(lc+0)*LDT + lr + 64] = b1.x;
        Bs[(lc+1)*LDT + lr + 64] = b1.y;
        Bs[(lc+2)*LDT + lr + 64] = b1.z;
        Bs[(lc+3)*LDT + lr + 64] = b1.w;
        __syncthreads();

        #pragma unroll
        for (int kk = 0; kk < BK; kk++) {
            float4 av0 = *(const float4*)&As[kk*LDT + ty*8];
            float4 av1 = *(const float4*)&As[kk*LDT + ty*8 + 4];
            float4 bv0 = *(const float4*)&Bs[kk*LDT + tx*8];
            float4 bv1 = *(const float4*)&Bs[kk*LDT + tx*8 + 4];
            float ar[8] = {av0.x, av0.y, av0.z, av0.w, av1.x, av1.y, av1.z, av1.w};
            float br[8] = {bv0.x, bv0.y, bv0.z, bv0.w, bv1.x, bv1.y, bv1.z, bv1.w};
            #pragma unroll
            for (int i = 0; i < 8; i++)
                #pragma unroll
                for (int j = 0; j < 8; j++)
                    acc[i][j] += ar[i] * br[j];
        }
    }

    #pragma unroll
    for (int i = 0; i < 8; i++) {
        float* crow = C + (size_t)(bm + ty*8 + i) * N + bn + tx*8;
        *(float4*)(crow)     = make_float4(acc[i][0], acc[i][1], acc[i][2], acc[i][3]);
        *(float4*)(crow + 4) = make_float4(acc[i][4], acc[i][5], acc[i][6], acc[i][7]);
    }
}

// ---------------------------------------------------------------------------
// Flash attention (fp32, causal). Grid (S/64, H, B), 256 threads.
// Q tile 64 rows, K/V tiles 64 keys, online softmax.
// Each thread: row r = tid/4, lane-group g = tid&3, owns 16 j-cols / 16 c-cols
// as 4 float4 chunks at offset 16t + 4g.
// ---------------------------------------------------------------------------
#define ATLD 68                                   // padded smem stride
#define ATTN_SMEM (4 * 64 * ATLD * sizeof(float)) // 69632 B

__global__ void __launch_bounds__(256) attn_kernel(
    const float* __restrict__ qkv, float* __restrict__ attn_out)
{
    extern __shared__ float sm[];
    float* Qs = sm;                  // [64][ATLD]  Qs[r][d] (pre-scaled)
    float* Kt = sm + 64*ATLD;        // [64][ATLD]  Kt[d][j] (transposed)
    float* Vs = sm + 2*64*ATLD;      // [64][ATLD]  Vs[j][d]
    float* Ps = sm + 3*64*ATLD;      // [64][ATLD]  Ps[r][j]

    const int qt  = blockIdx.x;
    const int h   = blockIdx.y;
    const int b   = blockIdx.z;
    const int tid = threadIdx.x;
    const int r   = tid >> 2;
    const int g   = tid & 3;
    const int q0  = qt * 64;

    const size_t rs = QKVDIM;  // row stride in qkv
    const float* Qg = qkv + (size_t)b * SEQ * rs + h * HDIM;
    const float* Kg = Qg + D_MODEL;
    const float* Vg = Qg + 2 * D_MODEL;

    // load Q tile, fold in 1/sqrt(d_k) = 0.125
    for (int idx = tid; idx < 64*16; idx += 256) {
        int row = idx >> 4;
        int d4  = (idx & 15) << 2;
        float4 q4 = *(const float4*)(Qg + (size_t)(q0 + row) * rs + d4);
        float* dst = &Qs[row*ATLD + d4];
        dst[0] = q4.x * 0.125f; dst[1] = q4.y * 0.125f;
        dst[2] = q4.z * 0.125f; dst[3] = q4.w * 0.125f;
    }

    float m = -1e30f, lpart = 0.f;
    float acc[16];
    #pragma unroll
    for (int i = 0; i < 16; i++) acc[i] = 0.f;

    for (int kt = 0; kt <= qt; kt++) {
        const int k0 = kt * 64;
        __syncthreads();
        // load K (transposed) and V tiles
        for (int idx = tid; idx < 64*16; idx += 256) {
            int row = idx >> 4;
            int d4  = (idx & 15) << 2;
            float4 k4 = *(const float4*)(Kg + (size_t)(k0 + row) * rs + d4);
            Kt[(d4+0)*ATLD + row] = k4.x;
            Kt[(d4+1)*ATLD + row] = k4.y;
            Kt[(d4+2)*ATLD + row] = k4.z;
            Kt[(d4+3)*ATLD + row] = k4.w;
            float4 v4 = *(const float4*)(Vg + (size_t)(k0 + row) * rs + d4);
            *(float4*)&Vs[row*ATLD + d4] = v4;
        }
        __syncthreads();

        // S = (Q*scale) @ K^T   (thread: 16 cols j = 16t + 4g + u)
        float s[16];
        #pragma unroll
        for (int i = 0; i < 16; i++) s[i] = 0.f;
        #pragma unroll 4
        for (int kk = 0; kk < 64; kk++) {
            float q = Qs[r*ATLD + kk];
            #pragma unroll
            for (int t = 0; t < 4; t++) {
                float4 kv = *(const float4*)&Kt[kk*ATLD + t*16 + g*4];
                s[t*4+0] += q * kv.x; s[t*4+1] += q * kv.y;
                s[t*4+2] += q * kv.z; s[t*4+3] += q * kv.w;
            }
        }
        // causal mask on diagonal tile
        if (kt == qt) {
            #pragma unroll
            for (int t = 0; t < 4; t++)
                #pragma unroll
                for (int u = 0; u < 4; u++)
                    if (t*16 + g*4 + u > r) s[t*4+u] = -1e30f;
        }
        // online softmax: row max across 4 lanes of this row
        float mloc = s[0];
        #pragma unroll
        for (int i = 1; i < 16; i++) mloc = fmaxf(mloc, s[i]);
        mloc = fmaxf(mloc, __shfl_xor_sync(0xffffffffu, mloc, 1));
        mloc = fmaxf(mloc, __shfl_xor_sync(0xffffffffu, mloc, 2));
        float mnew  = fmaxf(m, mloc);
        float alpha = __expf(m - mnew);
        m = mnew;
        float psum = 0.f;
        #pragma unroll
        for (int i = 0; i < 16; i++) {
            float p = __expf(s[i] - mnew);
            s[i] = p;
            psum += p;
        }
        lpart = lpart * alpha + psum;
        #pragma unroll
        for (int i = 0; i < 16; i++) acc[i] *= alpha;

        // publish P for this row's 4-lane group (all readers are in-warp)
        #pragma unroll
        for (int t = 0; t < 4; t++)
            *(float4*)&Ps[r*ATLD + t*16 + g*4] =
                make_float4(s[t*4+0], s[t*4+1], s[t*4+2], s[t*4+3]);
        __syncwarp();

        // O += P @ V   (thread: 16 cols c = 16t + 4g + u)
        #pragma unroll 4
        for (int j = 0; j < 64; j++) {
            float p = Ps[r*ATLD + j];
            #pragma unroll
            for (int t = 0; t < 4; t++) {
                float4 v = *(const float4*)&Vs[j*ATLD + t*16 + g*4];
                acc[t*4+0] += p * v.x; acc[t*4+1] += p * v.y;
                acc[t*4+2] += p * v.z; acc[t*4+3] += p * v.w;
            }
        }
    }

    // final normalize: l = sum over the 4 lanes' partials
    float l = lpart;
    l += __shfl_xor_sync(0xffffffffu, l, 1);
    l += __shfl_xor_sync(0xffffffffu, l, 2);
    float inv = 1.0f / l;

    float* Og = attn_out + (size_t)(b * SEQ + q0 + r) * D_MODEL + h * HDIM;
    #pragma unroll
    for (int t = 0; t < 4; t++)
        *(float4*)&Og[t*16 + g*4] = make_float4(acc[t*4+0]*inv, acc[t*4+1]*inv,
                                                acc[t*4+2]*inv, acc[t*4+3]*inv);
}

// ---------------------------------------------------------------------------
extern "C" void kernel_launch(void* const* d_in, const int* in_sizes, int n_in,
                              void* d_out, int out_size)
{
    const float* x      = (const float*)d_in[0];
    const float* w_qkv  = (const float*)d_in[1];
    const float* w_proj = (const float*)d_in[2];
    float* out = (float*)d_out;

    float *qkv, *attn;
    cudaGetSymbolAddress((void**)&qkv,  g_qkv);
    cudaGetSymbolAddress((void**)&attn, g_attn);

    cudaFuncSetAttribute(attn_kernel,
                         cudaFuncAttributeMaxDynamicSharedMemorySize,
                         (int)ATTN_SMEM);

    // 1) QKV projection: [4096,1024] x [3072,1024]^T -> g_qkv
    dim3 g1(QKVDIM/128, MROWS/128);
    sgemm_tn<<<g1, 256>>>(x, w_qkv, qkv, MROWS, QKVDIM, D_MODEL);

    // 2) causal flash attention -> g_attn [B,S,D]
    dim3 g2(SEQ/64, NHEAD, BATCH);
    attn_kernel<<<g2, 256, ATTN_SMEM>>>(qkv, attn);

    // 3) output projection: [4096,1024] x [1024,1024]^T -> out
    dim3 g3(D_MODEL/128, MROWS/128);
    sgemm_tn<<<g3, 256>>>(attn, w_proj, out, MROWS, D_MODEL, D_MODEL);
}

// round 3
// speedup vs baseline: 3.2737x; 3.2737x over previous
#include <cuda_runtime.h>
#include <cstdint>

#define D_MODEL 1024
#define NHEAD   16
#define HDIM    64
#define BATCH   2
#define SEQ     2048
#define MROWS   (BATCH*SEQ)       // 4096
#define QKVDIM  (3*D_MODEL)       // 3072

// Scratch (no cudaMalloc allowed)
__device__ float g_qkv [BATCH*SEQ*QKVDIM];   // 50 MB
__device__ float g_attn[BATCH*SEQ*D_MODEL];  // 16 MB

// ---------------------------------------------------------------------------
// helpers
// ---------------------------------------------------------------------------
static __device__ __forceinline__ uint32_t f2tf(float x) {
    uint32_t t;
    asm("cvt.rna.tf32.f32 %0, %1;" : "=r"(t) : "f"(x));
    return t;
}
static __device__ __forceinline__ float f2tff(float x) {
    return __uint_as_float(f2tf(x));
}
// D = A(16x8) * B(8x8) + D, tf32 inputs, fp32 accum
static __device__ __forceinline__ void mma8(
    float& c0, float& c1, float& c2, float& c3,
    uint32_t a0, uint32_t a1, uint32_t a2, uint32_t a3,
    uint32_t b0, uint32_t b1)
{
    asm volatile(
        "mma.sync.aligned.m16n8k8.row.col.f32.tf32.tf32.f32 "
        "{%0,%1,%2,%3}, {%4,%5,%6,%7}, {%8,%9}, {%0,%1,%2,%3};"
        : "+f"(c0), "+f"(c1), "+f"(c2), "+f"(c3)
        : "r"(a0), "r"(a1), "r"(a2), "r"(a3), "r"(b0), "r"(b1));
}

// ===========================================================================
// tf32 mma GEMM (TN):  C[m][n] = sum_k A[m*K+k] * B[n*K+k]
// BM=BN=128, BK=32, 256 thr, 8 warps (2m x 4n), warp tile 64x32.
// Smem word layout: tile[m][k] at  m*32 + (k ^ ((m&7)<<2))  -> conflict-free
// fragment loads AND in-bounds (k<32).
// ===========================================================================
#define GEMM_SMEM 65536   // 2 stages x (A 4096 + B 4096 words) x 4B

static __device__ __forceinline__ int swz(int m, int k) {
    return m * 32 + (k ^ ((m & 7) << 2));
}

__global__ void __launch_bounds__(256) gemm_tf32(
    const float* __restrict__ A, const float* __restrict__ B,
    float* __restrict__ C, int M, int N, int K)
{
    extern __shared__ float smg[];

    const int tid  = threadIdx.x;
    const int wid  = tid >> 5;
    const int lane = tid & 31;
    const int g    = lane >> 2;     // groupID 0..7
    const int ct   = lane & 3;      // ctid 0..3
    const int wm   = wid & 1;       // warp m (x64)
    const int wn   = wid >> 1;      // warp n (x32)
    const int bm   = blockIdx.y * 128;
    const int bn   = blockIdx.x * 128;

    const int row  = tid >> 1;      // 0..127
    const int half = tid & 1;       // 16-float half of the 32-k slab
    const float* Ap = A + (size_t)(bm + row) * K + half * 16;
    const float* Bp = B + (size_t)(bn + row) * K + half * 16;
    const int nkt = K / 32;

    float acc[4][4][4];
    #pragma unroll
    for (int i = 0; i < 4; i++)
        #pragma unroll
        for (int j = 0; j < 4; j++)
            #pragma unroll
            for (int e = 0; e < 4; e++) acc[i][j][e] = 0.f;

    float4 av[4], bv[4];
    // prologue: tile 0
    #pragma unroll
    for (int i = 0; i < 4; i++) {
        av[i] = *(const float4*)(Ap + i * 4);
        bv[i] = *(const float4*)(Bp + i * 4);
    }
    {
        float* As = smg;
        float* Bs = smg + 4096;
        #pragma unroll
        for (int i = 0; i < 4; i++) {
            int k = half * 16 + i * 4;
            *(float4*)&As[swz(row, k)] = make_float4(
                f2tff(av[i].x), f2tff(av[i].y), f2tff(av[i].z), f2tff(av[i].w));
            *(float4*)&Bs[swz(row, k)] = make_float4(
                f2tff(bv[i].x), f2tff(bv[i].y), f2tff(bv[i].z), f2tff(bv[i].w));
        }
    }
    __syncthreads();

    for (int kt = 0; kt < nkt; kt++) {
        const uint32_t* As = (const uint32_t*)(smg + (kt & 1) * 8192);
        const uint32_t* Bs = As + 4096;

        if (kt + 1 < nkt) {
            const float* Ap2 = Ap + (kt + 1) * 32;
            const float* Bp2 = Bp + (kt + 1) * 32;
            #pragma unroll
            for (int i = 0; i < 4; i++) {
                av[i] = *(const float4*)(Ap2 + i * 4);
                bv[i] = *(const float4*)(Bp2 + i * 4);
            }
        }

        #pragma unroll
        for (int ks = 0; ks < 4; ks++) {
            uint32_t a[4][4];
            #pragma unroll
            for (int mi = 0; mi < 4; mi++) {
                int m0 = wm * 64 + mi * 16 + g;
                a[mi][0] = As[swz(m0,     ks * 8 + ct)];
                a[mi][1] = As[swz(m0 + 8, ks * 8 + ct)];
                a[mi][2] = As[swz(m0,     ks * 8 + ct + 4)];
                a[mi][3] = As[swz(m0 + 8, ks * 8 + ct + 4)];
            }
            uint32_t bb[4][2];
            #pragma unroll
            for (int nt = 0; nt < 4; nt++) {
                int n0 = wn * 32 + nt * 8 + g;
                bb[nt][0] = Bs[swz(n0, ks * 8 + ct)];
                bb[nt][1] = Bs[swz(n0, ks * 8 + ct + 4)];
            }
            #pragma unroll
            for (int mi = 0; mi < 4; mi++)
                #pragma unroll
                for (int nt = 0; nt < 4; nt++)
                    mma8(acc[mi][nt][0], acc[mi][nt][1], acc[mi][nt][2], acc[mi][nt][3],
                         a[mi][0], a[mi][1], a[mi][2], a[mi][3],
                         bb[nt][0], bb[nt][1]);
        }

        if (kt + 1 < nkt) {
            __syncthreads();   // everyone done computing buf kt-1's successor reads
            float* As2 = smg + ((kt + 1) & 1) * 8192;
            float* Bs2 = As2 + 4096;
            #pragma unroll
            for (int i = 0; i < 4; i++) {
                int k = half * 16 + i * 4;
                *(float4*)&As2[swz(row, k)] = make_float4(
                    f2tff(av[i].x), f2tff(av[i].y), f2tff(av[i].z), f2tff(av[i].w));
                *(float4*)&Bs2[swz(row, k)] = make_float4(
                    f2tff(bv[i].x), f2tff(bv[i].y), f2tff(bv[i].z), f2tff(bv[i].w));
            }
            __syncthreads();
        }
    }

    // epilogue: direct float2 stores
    #pragma unroll
    for (int mi = 0; mi < 4; mi++) {
        int r0 = bm + wm * 64 + mi * 16 + g;
        #pragma unroll
        for (int nt = 0; nt < 4; nt++) {
            int c0 = bn + wn * 32 + nt * 8 + 2 * ct;
            *(float2*)&C[(size_t)r0 * N + c0]       = make_float2(acc[mi][nt][0], acc[mi][nt][1]);
            *(float2*)&C[(size_t)(r0 + 8) * N + c0] = make_float2(acc[mi][nt][2], acc[mi][nt][3]);
        }
    }
}

// ===========================================================================
// Flash attention, tf32 mma. Q tile 128, K/V tile 64.
// 8 warps, warp w owns rows [w*16, w*16+16) -> softmax is quad-shuffle only.
// Strides: Q/K/P = 68 (==4 mod 32), V = 72 (==8 mod 32): all fragment LDS
// conflict-free.
// ===========================================================================
#define LDQ 68
#define LDK 68
#define LDV 72
#define LDP 68
#define QS_W   (128*LDQ)                 // 8704
#define KS_W   (64*LDK)                  // 4352
#define VS_W   (64*LDV)                  // 4608
#define PS_W   (128*LDP)                 // 8704
#define ATTN_SMEM ((QS_W+KS_W+VS_W+PS_W)*4)   // 105472 B

__global__ void __launch_bounds__(256) attn_mma(
    const float* __restrict__ qkv, float* __restrict__ attn_out)
{
    extern __shared__ float sm[];
    float* Qs = sm;
    float* Ks = Qs + QS_W;
    float* Vs = Ks + KS_W;
    float* Ps = Vs + VS_W;
    const uint32_t* Qu = (const uint32_t*)Qs;
    const uint32_t* Ku = (const uint32_t*)Ks;
    const uint32_t* Vu = (const uint32_t*)Vs;
    const uint32_t* Pu = (const uint32_t*)Ps;

    const int qt  = (int)gridDim.x - 1 - (int)blockIdx.x;  // heavy blocks first
    const int h   = blockIdx.y;
    const int b   = blockIdx.z;
    const int tid = threadIdx.x;
    const int wid = tid >> 5;
    const int lane = tid & 31;
    const int g   = lane >> 2;
    const int ct  = lane & 3;
    const int q0  = qt * 128;
    const int rl  = wid * 16 + g;      // local row (low); high = rl+8

    const size_t rs = QKVDIM;
    const float* Qg = qkv + (size_t)b * SEQ * rs + h * HDIM;
    const float* Kg = Qg + D_MODEL;
    const float* Vg = Qg + 2 * D_MODEL;

    // load Q tile (128 x 64), scale by 0.125, tf32-round
    #pragma unroll
    for (int it = 0; it < 8; it++) {
        int idx = tid + it * 256;
        int row = idx >> 4;
        int d0  = (idx & 15) << 2;
        float4 q4 = *(const float4*)(Qg + (size_t)(q0 + row) * rs + d0);
        *(float4*)&Qs[row * LDQ + d0] = make_float4(
            f2tff(q4.x * 0.125f), f2tff(q4.y * 0.125f),
            f2tff(q4.z * 0.125f), f2tff(q4.w * 0.125f));
    }

    float m_lo = -1e30f, m_hi = -1e30f, l_lo = 0.f, l_hi = 0.f;
    float o[8][4];
    #pragma unroll
    for (int nt = 0; nt < 8; nt++)
        #pragma unroll
        for (int e = 0; e < 4; e++) o[nt][e] = 0.f;

    const int nkt = 2 * qt + 2;
    for (int kt = 0; kt < nkt; kt++) {
        const int k0 = kt * 64;
        __syncthreads();
        // load K, V tiles (64 x 64)
        #pragma unroll
        for (int it = 0; it < 4; it++) {
            int idx = tid + it * 256;
            int row = idx >> 4;
            int d0  = (idx & 15) << 2;
            float4 k4 = *(const float4*)(Kg + (size_t)(k0 + row) * rs + d0);
            *(float4*)&Ks[row * LDK + d0] = make_float4(
                f2tff(k4.x), f2tff(k4.y), f2tff(k4.z), f2tff(k4.w));
            float4 v4 = *(const float4*)(Vg + (size_t)(k0 + row) * rs + d0);
            *(float4*)&Vs[row * LDV + d0] = make_float4(
                f2tff(v4.x), f2tff(v4.y), f2tff(v4.z), f2tff(v4.w));
        }
        __syncthreads();

        if (k0 > q0 + wid * 16 + 15) continue;   // tile fully above diagonal

        // ---- S = Q K^T  (warp: m16 x n64, k=64) ----
        float s[8][4];
        #pragma unroll
        for (int nt = 0; nt < 8; nt++)
            #pragma unroll
            for (int e = 0; e < 4; e++) s[nt][e] = 0.f;

        #pragma unroll
        for (int ks = 0; ks < 8; ks++) {
            uint32_t a0 = Qu[rl * LDQ + ks * 8 + ct];
            uint32_t a1 = Qu[(rl + 8) * LDQ + ks * 8 + ct];
            uint32_t a2 = Qu[rl * LDQ + ks * 8 + ct + 4];
            uint32_t a3 = Qu[(rl + 8) * LDQ + ks * 8 + ct + 4];
            #pragma unroll
            for (int nt = 0; nt < 8; nt++) {
                uint32_t b0 = Ku[(nt * 8 + g) * LDK + ks * 8 + ct];
                uint32_t b1 = Ku[(nt * 8 + g) * LDK + ks * 8 + ct + 4];
                mma8(s[nt][0], s[nt][1], s[nt][2], s[nt][3], a0, a1, a2, a3, b0, b1);
            }
        }

        // ---- causal mask ----
        const int rglo = q0 + rl;
        const int rghi = rglo + 8;
        if (k0 + 63 > rglo) {
            #pragma unroll
            for (int nt = 0; nt < 8; nt++) {
                int key = k0 + nt * 8 + 2 * ct;
                if (key     > rglo) s[nt][0] = -1e30f;
                if (key + 1 > rglo) s[nt][1] = -1e30f;
                if (key     > rghi) s[nt][2] = -1e30f;
                if (key + 1 > rghi) s[nt][3] = -1e30f;
            }
        }

        // ---- online softmax (rows owned by this warp; quad reduce) ----
        float tlo = -1e30f, thi = -1e30f;
        #pragma unroll
        for (int nt = 0; nt < 8; nt++) {
            tlo = fmaxf(tlo, fmaxf(s[nt][0], s[nt][1]));
            thi = fmaxf(thi, fmaxf(s[nt][2], s[nt][3]));
        }
        tlo = fmaxf(tlo, __shfl_xor_sync(0xffffffffu, tlo, 1));
        tlo = fmaxf(tlo, __shfl_xor_sync(0xffffffffu, tlo, 2));
        thi = fmaxf(thi, __shfl_xor_sync(0xffffffffu, thi, 1));
        thi = fmaxf(thi, __shfl_xor_sync(0xffffffffu, thi, 2));

        float mn_lo = fmaxf(m_lo, tlo);
        float mn_hi = fmaxf(m_hi, thi);
        float al_lo = __expf(m_lo - mn_lo);
        float al_hi = __expf(m_hi - mn_hi);
        m_lo = mn_lo; m_hi = mn_hi;

        float ps_lo = 0.f, ps_hi = 0.f;
        #pragma unroll
        for (int nt = 0; nt < 8; nt++) {
            float p0 = __expf(s[nt][0] - mn_lo);
            float p1 = __expf(s[nt][1] - mn_lo);
            float p2 = __expf(s[nt][2] - mn_hi);
            float p3 = __expf(s[nt][3] - mn_hi);
            ps_lo += p0 + p1;
            ps_hi += p2 + p3;
            int col = nt * 8 + 2 * ct;
            *(float2*)&Ps[rl * LDP + col]       = make_float2(f2tff(p0), f2tff(p1));
            *(float2*)&Ps[(rl + 8) * LDP + col] = make_float2(f2tff(p2), f2tff(p3));
        }
        ps_lo += __shfl_xor_sync(0xffffffffu, ps_lo, 1);
        ps_lo += __shfl_xor_sync(0xffffffffu, ps_lo, 2);
        ps_hi += __shfl_xor_sync(0xffffffffu, ps_hi, 1);
        ps_hi += __shfl_xor_sync(0xffffffffu, ps_hi, 2);
        l_lo = l_lo * al_lo + ps_lo;
        l_hi = l_hi * al_hi + ps_hi;

        #pragma unroll
        for (int nt = 0; nt < 8; nt++) {
            o[nt][0] *= al_lo; o[nt][1] *= al_lo;
            o[nt][2] *= al_hi; o[nt][3] *= al_hi;
        }
        __syncwarp();

        // ---- O += P V  (warp: m16 x n64, k=64) ----
        #pragma unroll
        for (int ks = 0; ks < 8; ks++) {
            uint32_t a0 = Pu[rl * LDP + ks * 8 + ct];
            uint32_t a1 = Pu[(rl + 8) * LDP + ks * 8 + ct];
            uint32_t a2 = Pu[rl * LDP + ks * 8 + ct + 4];
            uint32_t a3 = Pu[(rl + 8) * LDP + ks * 8 + ct + 4];
            #pragma unroll
            for (int nt = 0; nt < 8; nt++) {
                uint32_t b0 = Vu[(ks * 8 + ct) * LDV + nt * 8 + g];
                uint32_t b1 = Vu[(ks * 8 + ct + 4) * LDV + nt * 8 + g];
                mma8(o[nt][0], o[nt][1], o[nt][2], o[nt][3], a0, a1, a2, a3, b0, b1);
            }
        }
    }

    // ---- finalize + store ----
    float inv_lo = 1.0f / l_lo;
    float inv_hi = 1.0f / l_hi;
    float* Og = attn_out + (size_t)(b * SEQ + q0) * D_MODEL + h * HDIM;
    #pragma unroll
    for (int nt = 0; nt < 8; nt++) {
        int col = nt * 8 + 2 * ct;
        *(float2*)&Og[(size_t)rl * D_MODEL + col] =
            make_float2(o[nt][0] * inv_lo, o[nt][1] * inv_lo);
        *(float2*)&Og[(size_t)(rl + 8) * D_MODEL + col] =
            make_float2(o[nt][2] * inv_hi, o[nt][3] * inv_hi);
    }
}

// ===========================================================================
extern "C" void kernel_launch(void* const* d_in, const int* in_sizes, int n_in,
                              void* d_out, int out_size)
{
    const float* x      = (const float*)d_in[0];
    const float* w_qkv  = (const float*)d_in[1];
    const float* w_proj = (const float*)d_in[2];
    float* out = (float*)d_out;

    float *qkv, *attn;
    cudaGetSymbolAddress((void**)&qkv,  g_qkv);
    cudaGetSymbolAddress((void**)&attn, g_attn);

    cudaFuncSetAttribute(gemm_tf32,
                         cudaFuncAttributeMaxDynamicSharedMemorySize, GEMM_SMEM);
    cudaFuncSetAttribute(attn_mma,
                         cudaFuncAttributeMaxDynamicSharedMemorySize, ATTN_SMEM);

    // 1) QKV projection
    dim3 g1(QKVDIM/128, MROWS/128);
    gemm_tf32<<<g1, 256, GEMM_SMEM>>>(x, w_qkv, qkv, MROWS, QKVDIM, D_MODEL);

    // 2) causal flash attention (tf32 mma)
    dim3 g2(SEQ/128, NHEAD, BATCH);
    attn_mma<<<g2, 256, ATTN_SMEM>>>(qkv, attn);

    // 3) output projection
    dim3 g3(D_MODEL/128, MROWS/128);
    gemm_tf32<<<g3, 256, GEMM_SMEM>>>(attn, w_proj, out, MROWS, D_MODEL, D_MODEL);
}